// round 11
// baseline (speedup 1.0000x reference)
#include <cuda_runtime.h>

#define BB 4
#define PP 2048
#define EE 1024
#define HH 16
#define HD 64
#define NB2 64          // bins
#define NC 11           // Taylor coefs c0..c10
#define NPART 8
#define NVP 32

// Scratch (fully overwritten every launch)
__device__ __align__(16) float g_Qs[BB*HH*PP];
__device__ __align__(16) float g_Ks[BB*HH*PP];
__device__ __align__(16) float g_Vpart[BB*NVP*EE];
__device__ __align__(16) float g_U[BB*HH*EE];       // [b][h][n]
__device__ __align__(16) float g_diag[BB*HH*PP];
__device__ __align__(16) float g_bt[BB*HH*NPART*NC*NB2];
__device__ __align__(8)  float2 g_mnmx[BB*HH];

__device__ __forceinline__ float ex2f(float x){
    float y; asm("ex2.approx.ftz.f32 %0, %1;" : "=f"(y) : "f"(x)); return y;
}

// ---------------------------------------------------------------------------
// K1: blocks [0,512): V partial column sums (scheduled first to overlap).
//     [512,8704): Q/K head row-sums, 2 rows/thread, coalesced stores.
// ---------------------------------------------------------------------------
__global__ void k_reduce(const float* __restrict__ Q, const float* __restrict__ K,
                         const float* __restrict__ V) {
    int bid = blockIdx.x;
    int tid = threadIdx.x;
    if (bid < 512) {
        int b = bid >> 7, r = bid & 127, pc = r >> 2, cg = r & 3;
        int c = cg * 256 + tid;
        const float* base = V + ((size_t)b * PP + pc * 64) * EE + c;
        float s = 0.f;
        #pragma unroll 16
        for (int p = 0; p < 64; p++) s += base[(size_t)p * EE];
        g_Vpart[(b * NVP + pc) * EE + c] = s;
    } else {
        int base = bid - 512;
        const float* src; float* dst;
        if (base < 4096) { src = Q; dst = g_Qs; }
        else             { src = K; dst = g_Ks; base -= 4096; }
        int bh = base >> 6;
        int ptile = base & 63;
        int b = bh >> 4, h = bh & 15;
        int seg = tid >> 4, lane16 = tid & 15;
        int p0 = ptile * 32 + seg;
        const float4* r0 = (const float4*)(src + (((size_t)(b * PP + p0)) << 10) + h * HD);
        const float4* r1 = (const float4*)(src + (((size_t)(b * PP + p0 + 16)) << 10) + h * HD);
        float4 v0 = r0[lane16];
        float4 v1 = r1[lane16];
        float s0 = (v0.x + v0.y) + (v0.z + v0.w);
        float s1 = (v1.x + v1.y) + (v1.z + v1.w);
        #pragma unroll
        for (int off = 8; off; off >>= 1) {
            s0 += __shfl_down_sync(0xffffffffu, s0, off, 16);
            s1 += __shfl_down_sync(0xffffffffu, s1, off, 16);
        }
        __shared__ float sm[32];
        if (lane16 == 0) { sm[seg] = s0; sm[16 + seg] = s1; }
        __syncthreads();
        if (tid < 32) dst[(bh << 11) + ptile * 32 + tid] = sm[tid];
    }
}

// ---------------------------------------------------------------------------
// min/max of ks[2048] for one bh, exact. 256 threads.
// ---------------------------------------------------------------------------
__device__ __forceinline__ void ks_minmax(const float4* kr4, int tid,
                                          float* s_mn, float* s_mx) {
    __shared__ float rmn[8], rmx[8];
    float mn = 3.4e38f, mx = -3.4e38f;
    #pragma unroll
    for (int i = 0; i < 2; i++) {
        float4 v = kr4[i * 256 + tid];
        mn = fminf(mn, fminf(fminf(v.x, v.y), fminf(v.z, v.w)));
        mx = fmaxf(mx, fmaxf(fmaxf(v.x, v.y), fmaxf(v.z, v.w)));
    }
    #pragma unroll
    for (int off = 16; off; off >>= 1) {
        mn = fminf(mn, __shfl_xor_sync(0xffffffffu, mn, off));
        mx = fmaxf(mx, __shfl_xor_sync(0xffffffffu, mx, off));
    }
    if ((tid & 31) == 0) { rmn[tid >> 5] = mn; rmx[tid >> 5] = mx; }
    __syncthreads();
    if (tid == 0) {
        float a = rmn[0], c = rmx[0];
        #pragma unroll
        for (int w = 1; w < 8; w++) { a = fminf(a, rmn[w]); c = fmaxf(c, rmx[w]); }
        *s_mn = a; *s_mx = c;
    }
    __syncthreads();
}

// ---------------------------------------------------------------------------
// K_mid: blocks [0,512): bin tables (64bh x 8 parts), 64 bins x 11 moments.
//        blocks [512,768): proj_u (b,h,nchunk).
// ---------------------------------------------------------------------------
__global__ void k_mid(const float* __restrict__ W) {
    int bid = blockIdx.x;
    int tid = threadIdx.x;
    if (bid < 512) {
        int bh = bid >> 3, part = bid & 7;
        __shared__ float s_mn, s_mx;
        __shared__ float tb[NC][NB2];
        const float4* kr4 = (const float4*)(g_Ks + ((size_t)bh << 11));
        ks_minmax(kr4, tid, &s_mn, &s_mx);
        for (int i = tid; i < NC * NB2; i += 256) ((float*)tb)[i] = 0.f;
        __syncthreads();

        float mn = s_mn, mx = s_mx;
        float w = fmaxf(mx - mn, 1e-20f) * (1.0f / NB2);
        float invw = 1.0f / w;

        float k = g_Ks[((size_t)bh << 11) + (part << 8) + tid];
        int idx = (int)((k - mn) * invw);
        idx = max(0, min(NB2 - 1, idx));
        float kb = mn + ((float)idx + 0.5f) * w;
        float d  = k - kb;
        float t = 1.0f;
        atomicAdd(&tb[0][idx], 1.0f);
        const float rc[10] = {1.f, 0.5f, 1.f/3.f, 0.25f, 0.2f, 1.f/6.f,
                              1.f/7.f, 0.125f, 1.f/9.f, 0.1f};
        #pragma unroll
        for (int c = 1; c <= 10; c++) {
            t *= d * rc[c - 1];
            atomicAdd(&tb[c][idx], t);
        }
        __syncthreads();

        float* out = g_bt + (size_t)((bh * NPART + part) * NC) * NB2;
        for (int i = tid; i < NC * NB2; i += 256) out[i] = ((float*)tb)[i];
        if (part == 0 && tid == 0) g_mnmx[bh] = make_float2(mn, mx);
    } else {
        int blk = bid - 512;
        int b = blk >> 6, h = (blk >> 2) & 15, nc = blk & 3;
        __shared__ float vs[HD];
        if (tid < HD) {
            float s = 0.f;
            #pragma unroll
            for (int pc = 0; pc < NVP; pc++)
                s += g_Vpart[(b * NVP + pc) * EE + h * HD + tid];
            vs[tid] = s;
        }
        __syncthreads();
        int n = nc * 256 + tid;
        const float4* wr = (const float4*)(W + (size_t)n * EE + h * HD);
        float acc = 0.f;
        #pragma unroll
        for (int e = 0; e < 16; e++) {
            float4 w4 = wr[e];
            acc += w4.x * vs[4*e] + w4.y * vs[4*e+1] + w4.z * vs[4*e+2] + w4.w * vs[4*e+3];
        }
        g_U[((b * HH + h) << 10) + n] = acc;
    }
}

// ---------------------------------------------------------------------------
// K3: softmax diagonal: 64 bins x degree-10 Taylor, geometric e-recurrence
//   with ex2 restart every 16 bins. grid 512 = 64bh x 8 chunks; 256 threads.
// ---------------------------------------------------------------------------
__global__ void __launch_bounds__(256) k_softmax_diag() {
    int bh = blockIdx.x >> 3, ic = blockIdx.x & 7;
    int tid = threadIdx.x;
    __shared__ __align__(16) float cf[NB2][12];
    __shared__ float2 s_mm;
    if (tid == 0) s_mm = g_mnmx[bh];

    {
        const float* bt = g_bt + (size_t)(bh * NPART * NC) * NB2;
        for (int i = tid; i < NC * NB2; i += 256) {
            int c = i >> 6, bin = i & 63;
            float s = 0.f;
            #pragma unroll
            for (int part = 0; part < NPART; part++)
                s += bt[(size_t)(part * NC) * NB2 + i];
            cf[bin][c] = s;
        }
        for (int i = tid; i < NB2; i += 256) cf[i][11] = 0.f;
    }
    __syncthreads();

    float mn = s_mm.x, mx = s_mm.y;
    float w = fmaxf(mx - mn, 1e-20f) * (1.0f / NB2);

    const float L2E = 1.44269504088896340736f;
    int i = (ic << 8) + tid;
    float a  = 0.125f * g_Qs[((size_t)bh << 11) + i];
    float a2 = a * L2E;
    float nM = -((a2 >= 0.f) ? a2 * mx : a2 * mn);
    float rd = ex2f(a2 * w);

    float acc0 = 0.f, acc1 = 0.f;
    #pragma unroll 1
    for (int seg = 0; seg < 4; seg++) {
        float kb = fmaf((float)(seg * 16) + 0.5f, w, mn);
        float e  = ex2f(fmaf(a2, kb, nM));
        float accs = 0.f;
        #pragma unroll
        for (int t = 0; t < 16; t++) {
            int bin = seg * 16 + t;
            float4 A = *(const float4*)&cf[bin][0];
            float4 B = *(const float4*)&cf[bin][4];
            float4 C = *(const float4*)&cf[bin][8];
            float p = C.z;
            p = fmaf(a, p, C.y);
            p = fmaf(a, p, C.x);
            p = fmaf(a, p, B.w);
            p = fmaf(a, p, B.z);
            p = fmaf(a, p, B.y);
            p = fmaf(a, p, B.x);
            p = fmaf(a, p, A.w);
            p = fmaf(a, p, A.z);
            p = fmaf(a, p, A.y);
            p = fmaf(a, p, A.x);
            accs = fmaf(e, p, accs);
            e *= rd;
        }
        if (seg & 1) acc1 += accs; else acc0 += accs;
    }
    float denom = acc0 + acc1;

    float ki  = g_Ks[((size_t)bh << 11) + i];
    float num = ex2f(fmaf(a2, ki, nM));
    g_diag[((size_t)bh << 11) + i] = num / denom;
}

// ---------------------------------------------------------------------------
// K4: Y[b,p,n] = sum_h diag[b,h,p]*U[b,h,n] + bias[n].
//   Block tile 64p x 256n; warp = one 8-p group (d loads are pure
//   broadcast), lane = 8n. Thread = 8p x 8n (64 acc regs).
//   Per h per warp: 2 broadcast LDS (d) + 2 LDS (u) for 64 FMA-instr.
//   grid 512 = 4b x 32pt x 4nt; 256 threads; 2 blocks/SM.
// ---------------------------------------------------------------------------
__global__ void __launch_bounds__(256, 2) k_out(const float* __restrict__ bias,
                                                float* __restrict__ Y) {
    int nt = blockIdx.x & 3;
    int pt = (blockIdx.x >> 2) & 31;
    int b  = blockIdx.x >> 7;
    int tid = threadIdx.x;

    __shared__ __align__(16) float u_s[HH][256];
    __shared__ __align__(16) float d_s[HH][64];

    // load U tile: 16h x 256n = 1024 float4
    #pragma unroll
    for (int r = 0; r < 4; r++) {
        int idx = r * 256 + tid;
        int h = idx >> 6, q = idx & 63;
        ((float4*)u_s[h])[q] =
            ((const float4*)(g_U + ((b * HH + h) << 10) + nt * 256))[q];
    }
    // load diag tile: 16h x 64p = 256 float4 (1 per thread)
    {
        int h = tid >> 4, q = tid & 15;
        ((float4*)d_s[h])[q] =
            ((const float4*)(g_diag + (((size_t)(b * HH + h)) << 11) + pt * 64))[q];
    }
    __syncthreads();

    int wrp = tid >> 5;         // warp = p-group of 8
    int nq  = tid & 31;         // lane = n-group of 8
    int nblk = nt * 256 + nq * 8;

    float4 b0 = *(const float4*)(bias + nblk);
    float4 b1 = *(const float4*)(bias + nblk + 4);
    float acc[8][8];
    #pragma unroll
    for (int p = 0; p < 8; p++) {
        acc[p][0] = b0.x; acc[p][1] = b0.y; acc[p][2] = b0.z; acc[p][3] = b0.w;
        acc[p][4] = b1.x; acc[p][5] = b1.y; acc[p][6] = b1.z; acc[p][7] = b1.w;
    }

    #pragma unroll
    for (int h = 0; h < HH; h++) {
        float4 d0  = *(const float4*)&d_s[h][wrp * 8];       // broadcast
        float4 d1  = *(const float4*)&d_s[h][wrp * 8 + 4];   // broadcast
        float4 u01 = ((const float4*)u_s[h])[nq * 2];
        float4 u23 = ((const float4*)u_s[h])[nq * 2 + 1];
        float u[8] = {u01.x, u01.y, u01.z, u01.w, u23.x, u23.y, u23.z, u23.w};
        float dp[8] = {d0.x, d0.y, d0.z, d0.w, d1.x, d1.y, d1.z, d1.w};
        #pragma unroll
        for (int p = 0; p < 8; p++)
            #pragma unroll
            for (int j = 0; j < 8; j++)
                acc[p][j] = fmaf(dp[p], u[j], acc[p][j]);
    }

    #pragma unroll
    for (int p = 0; p < 8; p++) {
        float* yrow = Y + (((size_t)(b * PP + pt * 64 + wrp * 8 + p)) << 10) + nblk;
        ((float4*)yrow)[0] = make_float4(acc[p][0], acc[p][1], acc[p][2], acc[p][3]);
        ((float4*)yrow)[1] = make_float4(acc[p][4], acc[p][5], acc[p][6], acc[p][7]);
    }
}

extern "C" void kernel_launch(void* const* d_in, const int* in_sizes, int n_in,
                              void* d_out, int out_size) {
    const float* Q    = (const float*)d_in[0];
    const float* K    = (const float*)d_in[1];
    const float* V    = (const float*)d_in[2];
    const float* W    = (const float*)d_in[3];
    const float* bias = (const float*)d_in[4];
    float* Y = (float*)d_out;

    k_reduce<<<8704, 256>>>(Q, K, V);
    k_mid<<<768, 256>>>(W);
    k_softmax_diag<<<512, 256>>>();
    k_out<<<512, 256>>>(bias, Y);
}

// round 13
// speedup vs baseline: 1.0492x; 1.0492x over previous
#include <cuda_runtime.h>

#define BB 4
#define PP 2048
#define EE 1024
#define HH 16
#define HD 64
#define NB2 64          // bins
#define NC 11           // Taylor coefs c0..c10
#define NPART 8
#define NVP 32

// Scratch (fully overwritten every launch)
__device__ __align__(16) float g_Qs[BB*HH*PP];
__device__ __align__(16) float g_Ks[BB*HH*PP];
__device__ __align__(16) float g_Vpart[BB*NVP*EE];
__device__ __align__(16) float g_U[BB*HH*EE];       // [b][h][n]
__device__ __align__(16) float g_diag[BB*HH*PP];
__device__ __align__(16) float g_bt[BB*HH*NPART*NC*NB2];
__device__ __align__(8)  float2 g_mnmx[BB*HH];

__device__ __forceinline__ float ex2f(float x){
    float y; asm("ex2.approx.ftz.f32 %0, %1;" : "=f"(y) : "f"(x)); return y;
}

// ---------------------------------------------------------------------------
// K1a: Q/K head row-sums. 8192 blocks; 2 rows/thread; coalesced stores.
// ---------------------------------------------------------------------------
__global__ void k_reduce_qk(const float* __restrict__ Q, const float* __restrict__ K) {
    int base = blockIdx.x;
    int tid = threadIdx.x;
    const float* src; float* dst;
    if (base < 4096) { src = Q; dst = g_Qs; }
    else             { src = K; dst = g_Ks; base -= 4096; }
    int bh = base >> 6;
    int ptile = base & 63;
    int b = bh >> 4, h = bh & 15;
    int seg = tid >> 4, lane16 = tid & 15;
    int p0 = ptile * 32 + seg;
    const float4* r0 = (const float4*)(src + (((size_t)(b * PP + p0)) << 10) + h * HD);
    const float4* r1 = (const float4*)(src + (((size_t)(b * PP + p0 + 16)) << 10) + h * HD);
    float4 v0 = r0[lane16];
    float4 v1 = r1[lane16];
    float s0 = (v0.x + v0.y) + (v0.z + v0.w);
    float s1 = (v1.x + v1.y) + (v1.z + v1.w);
    #pragma unroll
    for (int off = 8; off; off >>= 1) {
        s0 += __shfl_down_sync(0xffffffffu, s0, off, 16);
        s1 += __shfl_down_sync(0xffffffffu, s1, off, 16);
    }
    __shared__ float sm[32];
    if (lane16 == 0) { sm[seg] = s0; sm[16 + seg] = s1; }
    __syncthreads();
    if (tid < 32) dst[(bh << 11) + ptile * 32 + tid] = sm[tid];
}

// ---------------------------------------------------------------------------
// K1b: V partial column sums. 512 blocks.
// ---------------------------------------------------------------------------
__global__ void k_reduce_v(const float* __restrict__ V) {
    int bid = blockIdx.x;
    int tid = threadIdx.x;
    int b = bid >> 7, r = bid & 127, pc = r >> 2, cg = r & 3;
    int c = cg * 256 + tid;
    const float* base = V + ((size_t)b * PP + pc * 64) * EE + c;
    float s = 0.f;
    #pragma unroll 16
    for (int p = 0; p < 64; p++) s += base[(size_t)p * EE];
    g_Vpart[(b * NVP + pc) * EE + c] = s;
}

// ---------------------------------------------------------------------------
// min/max of ks[2048] for one bh, exact. 256 threads.
// ---------------------------------------------------------------------------
__device__ __forceinline__ void ks_minmax(const float4* kr4, int tid,
                                          float* s_mn, float* s_mx) {
    __shared__ float rmn[8], rmx[8];
    float mn = 3.4e38f, mx = -3.4e38f;
    #pragma unroll
    for (int i = 0; i < 2; i++) {
        float4 v = kr4[i * 256 + tid];
        mn = fminf(mn, fminf(fminf(v.x, v.y), fminf(v.z, v.w)));
        mx = fmaxf(mx, fmaxf(fmaxf(v.x, v.y), fmaxf(v.z, v.w)));
    }
    #pragma unroll
    for (int off = 16; off; off >>= 1) {
        mn = fminf(mn, __shfl_xor_sync(0xffffffffu, mn, off));
        mx = fmaxf(mx, __shfl_xor_sync(0xffffffffu, mx, off));
    }
    if ((tid & 31) == 0) { rmn[tid >> 5] = mn; rmx[tid >> 5] = mx; }
    __syncthreads();
    if (tid == 0) {
        float a = rmn[0], c = rmx[0];
        #pragma unroll
        for (int w = 1; w < 8; w++) { a = fminf(a, rmn[w]); c = fmaxf(c, rmx[w]); }
        *s_mn = a; *s_mx = c;
    }
    __syncthreads();
}

// ---------------------------------------------------------------------------
// K_mid: blocks [0,512): bin tables (64bh x 8 parts), 64 bins x 11 moments.
//        blocks [512,768): proj_u (b,h,nchunk).
// ---------------------------------------------------------------------------
__global__ void k_mid(const float* __restrict__ W) {
    int bid = blockIdx.x;
    int tid = threadIdx.x;
    if (bid < 512) {
        int bh = bid >> 3, part = bid & 7;
        __shared__ float s_mn, s_mx;
        __shared__ float tb[NC][NB2];
        const float4* kr4 = (const float4*)(g_Ks + ((size_t)bh << 11));
        ks_minmax(kr4, tid, &s_mn, &s_mx);
        for (int i = tid; i < NC * NB2; i += 256) ((float*)tb)[i] = 0.f;
        __syncthreads();

        float mn = s_mn, mx = s_mx;
        float w = fmaxf(mx - mn, 1e-20f) * (1.0f / NB2);
        float invw = 1.0f / w;

        float k = g_Ks[((size_t)bh << 11) + (part << 8) + tid];
        int idx = (int)((k - mn) * invw);
        idx = max(0, min(NB2 - 1, idx));
        float kb = mn + ((float)idx + 0.5f) * w;
        float d  = k - kb;
        float t = 1.0f;
        atomicAdd(&tb[0][idx], 1.0f);
        const float rc[10] = {1.f, 0.5f, 1.f/3.f, 0.25f, 0.2f, 1.f/6.f,
                              1.f/7.f, 0.125f, 1.f/9.f, 0.1f};
        #pragma unroll
        for (int c = 1; c <= 10; c++) {
            t *= d * rc[c - 1];
            atomicAdd(&tb[c][idx], t);
        }
        __syncthreads();

        float* out = g_bt + (size_t)((bh * NPART + part) * NC) * NB2;
        for (int i = tid; i < NC * NB2; i += 256) out[i] = ((float*)tb)[i];
        if (part == 0 && tid == 0) g_mnmx[bh] = make_float2(mn, mx);
    } else {
        int blk = bid - 512;
        int b = blk >> 6, h = (blk >> 2) & 15, nc = blk & 3;
        __shared__ float vs[HD];
        if (tid < HD) {
            float s = 0.f;
            #pragma unroll
            for (int pc = 0; pc < NVP; pc++)
                s += g_Vpart[(b * NVP + pc) * EE + h * HD + tid];
            vs[tid] = s;
        }
        __syncthreads();
        int n = nc * 256 + tid;
        const float4* wr = (const float4*)(W + (size_t)n * EE + h * HD);
        float acc = 0.f;
        #pragma unroll
        for (int e = 0; e < 16; e++) {
            float4 w4 = wr[e];
            acc += w4.x * vs[4*e] + w4.y * vs[4*e+1] + w4.z * vs[4*e+2] + w4.w * vs[4*e+3];
        }
        g_U[((b * HH + h) << 10) + n] = acc;
    }
}

// ---------------------------------------------------------------------------
// K3: softmax diagonal: 64 bins x degree-10 Taylor, geometric e-recurrence
//   with ex2 restart every 16 bins. grid 512 = 64bh x 8 chunks; 256 threads.
// ---------------------------------------------------------------------------
__global__ void __launch_bounds__(256) k_softmax_diag() {
    int bh = blockIdx.x >> 3, ic = blockIdx.x & 7;
    int tid = threadIdx.x;
    __shared__ __align__(16) float cf[NB2][12];
    __shared__ float2 s_mm;
    if (tid == 0) s_mm = g_mnmx[bh];

    {
        const float* bt = g_bt + (size_t)(bh * NPART * NC) * NB2;
        for (int i = tid; i < NC * NB2; i += 256) {
            int c = i >> 6, bin = i & 63;
            float s = 0.f;
            #pragma unroll
            for (int part = 0; part < NPART; part++)
                s += bt[(size_t)(part * NC) * NB2 + i];
            cf[bin][c] = s;
        }
        for (int i = tid; i < NB2; i += 256) cf[i][11] = 0.f;
    }
    __syncthreads();

    float mn = s_mm.x, mx = s_mm.y;
    float w = fmaxf(mx - mn, 1e-20f) * (1.0f / NB2);

    const float L2E = 1.44269504088896340736f;
    int i = (ic << 8) + tid;
    float a  = 0.125f * g_Qs[((size_t)bh << 11) + i];
    float a2 = a * L2E;
    float nM = -((a2 >= 0.f) ? a2 * mx : a2 * mn);
    float rd = ex2f(a2 * w);

    float acc0 = 0.f, acc1 = 0.f;
    #pragma unroll 1
    for (int seg = 0; seg < 4; seg++) {
        float kb = fmaf((float)(seg * 16) + 0.5f, w, mn);
        float e  = ex2f(fmaf(a2, kb, nM));
        float accs = 0.f;
        #pragma unroll
        for (int t = 0; t < 16; t++) {
            int bin = seg * 16 + t;
            float4 A = *(const float4*)&cf[bin][0];
            float4 B = *(const float4*)&cf[bin][4];
            float4 C = *(const float4*)&cf[bin][8];
            float p = C.z;
            p = fmaf(a, p, C.y);
            p = fmaf(a, p, C.x);
            p = fmaf(a, p, B.w);
            p = fmaf(a, p, B.z);
            p = fmaf(a, p, B.y);
            p = fmaf(a, p, B.x);
            p = fmaf(a, p, A.w);
            p = fmaf(a, p, A.z);
            p = fmaf(a, p, A.y);
            p = fmaf(a, p, A.x);
            accs = fmaf(e, p, accs);
            e *= rd;
        }
        if (seg & 1) acc1 += accs; else acc0 += accs;
    }
    float denom = acc0 + acc1;

    float ki  = g_Ks[((size_t)bh << 11) + i];
    float num = ex2f(fmaf(a2, ki, nM));
    g_diag[((size_t)bh << 11) + i] = num / denom;
}

// ---------------------------------------------------------------------------
// K4: Y[b,p,n] = sum_h diag[b,h,p]*U[b,h,n] + bias[n].
//   R4-proven design: grid 256 = 4b x 64pt (32p); thread = 4 consecutive n
//   with u4[16] in registers (coalesced LDG.128 from g_U[b][h][n]); diag
//   broadcast from a 2KB smem tile; no mainloop syncs.
// ---------------------------------------------------------------------------
__global__ void __launch_bounds__(256) k_out(const float* __restrict__ bias,
                                             float* __restrict__ Y) {
    int pt = blockIdx.x & 63;
    int b  = blockIdx.x >> 6;
    int tid = threadIdx.x;
    __shared__ float dsm[HH * 32];
    #pragma unroll
    for (int r = 0; r < 2; r++) {
        int idx = r * 256 + tid;
        int h = idx >> 5, pl = idx & 31;
        dsm[h * 32 + pl] = g_diag[(((size_t)(b * HH + h)) << 11) + pt * 32 + pl];
    }
    __syncthreads();

    int n0 = tid << 2;
    float4 u4[HH];
    #pragma unroll
    for (int h = 0; h < HH; h++)
        u4[h] = *(const float4*)(g_U + ((b * HH + h) << 10) + n0);
    float4 bn = *(const float4*)(bias + n0);

    float4* out = (float4*)(Y + (((size_t)(b * PP + pt * 32)) << 10) + n0);
    #pragma unroll 2
    for (int p = 0; p < 32; p++) {
        float4 acc = bn;
        #pragma unroll
        for (int h = 0; h < HH; h++) {
            float d = dsm[h * 32 + p];
            acc.x = fmaf(u4[h].x, d, acc.x);
            acc.y = fmaf(u4[h].y, d, acc.y);
            acc.z = fmaf(u4[h].z, d, acc.z);
            acc.w = fmaf(u4[h].w, d, acc.w);
        }
        out[(size_t)p << 8] = acc;
    }
}

extern "C" void kernel_launch(void* const* d_in, const int* in_sizes, int n_in,
                              void* d_out, int out_size) {
    const float* Q    = (const float*)d_in[0];
    const float* K    = (const float*)d_in[1];
    const float* V    = (const float*)d_in[2];
    const float* W    = (const float*)d_in[3];
    const float* bias = (const float*)d_in[4];
    float* Y = (float*)d_out;

    k_reduce_qk<<<8192, 256>>>(Q, K);
    k_reduce_v<<<512, 256>>>(V);
    k_mid<<<768, 256>>>(W);
    k_softmax_diag<<<512, 256>>>();
    k_out<<<256, 256>>>(bias, Y);
}

// round 14
// speedup vs baseline: 1.1873x; 1.1317x over previous
#include <cuda_runtime.h>

#define BB 4
#define PP 2048
#define EE 1024
#define HH 16
#define HD 64
#define NB2 64          // ks bins
#define NC 11           // Taylor coefs c0..c10
#define NPART 8
#define NVP 32
#define NNODE 512       // interpolation nodes per bh

// Scratch (fully overwritten every launch)
__device__ __align__(16) float g_Qs[BB*HH*PP];
__device__ __align__(16) float g_Ks[BB*HH*PP];
__device__ __align__(16) float g_Vpart[BB*NVP*EE];
__device__ __align__(16) float g_U[BB*HH*EE];       // [b][h][n]
__device__ __align__(16) float g_diag[BB*HH*PP];
__device__ __align__(16) float g_bt[BB*HH*NPART*NC*NB2];
__device__ __align__(16) float g_tab[BB*HH*NNODE];  // log2-denominator nodes
__device__ __align__(8)  float2 g_mnmx[BB*HH];      // ks min/max
__device__ __align__(16) float4 g_qmm[BB*HH];       // (amin2, h2, 1/h2, pad)

__device__ __forceinline__ float ex2f(float x){
    float y; asm("ex2.approx.ftz.f32 %0, %1;" : "=f"(y) : "f"(x)); return y;
}
__device__ __forceinline__ float lg2f(float x){
    float y; asm("lg2.approx.f32 %0, %1;" : "=f"(y) : "f"(x)); return y;
}

// ---------------------------------------------------------------------------
// K1: blocks [0,512): V partial column sums (first: overlap with QK stream).
//     [512,8704): Q/K head row-sums, 2 rows/thread, coalesced stores.
// ---------------------------------------------------------------------------
__global__ void k_reduce(const float* __restrict__ Q, const float* __restrict__ K,
                         const float* __restrict__ V) {
    int bid = blockIdx.x;
    int tid = threadIdx.x;
    if (bid < 512) {
        int b = bid >> 7, r = bid & 127, pc = r >> 2, cg = r & 3;
        int c = cg * 256 + tid;
        const float* base = V + ((size_t)b * PP + pc * 64) * EE + c;
        float s = 0.f;
        #pragma unroll 16
        for (int p = 0; p < 64; p++) s += base[(size_t)p * EE];
        g_Vpart[(b * NVP + pc) * EE + c] = s;
    } else {
        int base = bid - 512;
        const float* src; float* dst;
        if (base < 4096) { src = Q; dst = g_Qs; }
        else             { src = K; dst = g_Ks; base -= 4096; }
        int bh = base >> 6;
        int ptile = base & 63;
        int b = bh >> 4, h = bh & 15;
        int seg = tid >> 4, lane16 = tid & 15;
        int p0 = ptile * 32 + seg;
        const float4* r0 = (const float4*)(src + (((size_t)(b * PP + p0)) << 10) + h * HD);
        const float4* r1 = (const float4*)(src + (((size_t)(b * PP + p0 + 16)) << 10) + h * HD);
        float4 v0 = r0[lane16];
        float4 v1 = r1[lane16];
        float s0 = (v0.x + v0.y) + (v0.z + v0.w);
        float s1 = (v1.x + v1.y) + (v1.z + v1.w);
        #pragma unroll
        for (int off = 8; off; off >>= 1) {
            s0 += __shfl_down_sync(0xffffffffu, s0, off, 16);
            s1 += __shfl_down_sync(0xffffffffu, s1, off, 16);
        }
        __shared__ float sm[32];
        if (lane16 == 0) { sm[seg] = s0; sm[16 + seg] = s1; }
        __syncthreads();
        if (tid < 32) dst[(bh << 11) + ptile * 32 + tid] = sm[tid];
    }
}

// ---------------------------------------------------------------------------
// min/max of arr[2048], exact. 256 threads.
// ---------------------------------------------------------------------------
__device__ __forceinline__ void ks_minmax(const float4* kr4, int tid,
                                          float* s_mn, float* s_mx) {
    __shared__ float rmn[8], rmx[8];
    float mn = 3.4e38f, mx = -3.4e38f;
    #pragma unroll
    for (int i = 0; i < 2; i++) {
        float4 v = kr4[i * 256 + tid];
        mn = fminf(mn, fminf(fminf(v.x, v.y), fminf(v.z, v.w)));
        mx = fmaxf(mx, fmaxf(fmaxf(v.x, v.y), fmaxf(v.z, v.w)));
    }
    #pragma unroll
    for (int off = 16; off; off >>= 1) {
        mn = fminf(mn, __shfl_xor_sync(0xffffffffu, mn, off));
        mx = fmaxf(mx, __shfl_xor_sync(0xffffffffu, mx, off));
    }
    if ((tid & 31) == 0) { rmn[tid >> 5] = mn; rmx[tid >> 5] = mx; }
    __syncthreads();
    if (tid == 0) {
        float a = rmn[0], c = rmx[0];
        #pragma unroll
        for (int w = 1; w < 8; w++) { a = fminf(a, rmn[w]); c = fmaxf(c, rmx[w]); }
        *s_mn = a; *s_mx = c;
    }
    __syncthreads();
}

// ---------------------------------------------------------------------------
// K_mid: [0,512): ks bin tables (64bh x 8 parts), 64 bins x 11 moments.
//        [512,768): proj_u. [768,832): Qs min/max -> node-grid params.
// ---------------------------------------------------------------------------
__global__ void k_mid(const float* __restrict__ W) {
    int bid = blockIdx.x;
    int tid = threadIdx.x;
    if (bid < 512) {
        int bh = bid >> 3, part = bid & 7;
        __shared__ float s_mn, s_mx;
        __shared__ float tb[NC][NB2];
        const float4* kr4 = (const float4*)(g_Ks + ((size_t)bh << 11));
        ks_minmax(kr4, tid, &s_mn, &s_mx);
        for (int i = tid; i < NC * NB2; i += 256) ((float*)tb)[i] = 0.f;
        __syncthreads();

        float mn = s_mn, mx = s_mx;
        float w = fmaxf(mx - mn, 1e-20f) * (1.0f / NB2);
        float invw = 1.0f / w;

        float k = g_Ks[((size_t)bh << 11) + (part << 8) + tid];
        int idx = (int)((k - mn) * invw);
        idx = max(0, min(NB2 - 1, idx));
        float kb = mn + ((float)idx + 0.5f) * w;
        float d  = k - kb;
        float t = 1.0f;
        atomicAdd(&tb[0][idx], 1.0f);
        const float rc[10] = {1.f, 0.5f, 1.f/3.f, 0.25f, 0.2f, 1.f/6.f,
                              1.f/7.f, 0.125f, 1.f/9.f, 0.1f};
        #pragma unroll
        for (int c = 1; c <= 10; c++) {
            t *= d * rc[c - 1];
            atomicAdd(&tb[c][idx], t);
        }
        __syncthreads();

        float* out = g_bt + (size_t)((bh * NPART + part) * NC) * NB2;
        for (int i = tid; i < NC * NB2; i += 256) out[i] = ((float*)tb)[i];
        if (part == 0 && tid == 0) g_mnmx[bh] = make_float2(mn, mx);
    } else if (bid < 768) {
        int blk = bid - 512;
        int b = blk >> 6, h = (blk >> 2) & 15, nc = blk & 3;
        __shared__ float vs[HD];
        if (tid < HD) {
            float s = 0.f;
            #pragma unroll
            for (int pc = 0; pc < NVP; pc++)
                s += g_Vpart[(b * NVP + pc) * EE + h * HD + tid];
            vs[tid] = s;
        }
        __syncthreads();
        int n = nc * 256 + tid;
        const float4* wr = (const float4*)(W + (size_t)n * EE + h * HD);
        float acc = 0.f;
        #pragma unroll
        for (int e = 0; e < 16; e++) {
            float4 w4 = wr[e];
            acc += w4.x * vs[4*e] + w4.y * vs[4*e+1] + w4.z * vs[4*e+2] + w4.w * vs[4*e+3];
        }
        g_U[((b * HH + h) << 10) + n] = acc;
    } else {
        int bh = bid - 768;
        __shared__ float s_mn, s_mx;
        ks_minmax((const float4*)(g_Qs + ((size_t)bh << 11)), tid, &s_mn, &s_mx);
        if (tid == 0) {
            const float C2 = 0.125f * 1.44269504088896340736f;
            float amin2 = C2 * s_mn, amax2 = C2 * s_mx;
            if (amin2 > amax2) { float t2 = amin2; amin2 = amax2; amax2 = t2; }
            float h2 = fmaxf(amax2 - amin2, 1e-20f) * (1.0f / 507.0f);
            g_qmm[bh] = make_float4(amin2, h2, 1.0f / h2, 0.f);
        }
    }
}

// ---------------------------------------------------------------------------
// K_nodes: evaluate g(a2) = log2 sum_j 2^(a2*ks_j) at 512 nodes per bh via
//   binned deg-10 Taylor. Nodes span [amin2-2h, amax2+2h].
//   grid 128 = 64bh x 2 halves; 256 threads = 1 node each.
// ---------------------------------------------------------------------------
__global__ void __launch_bounds__(256) k_nodes() {
    int bh = blockIdx.x >> 1, half = blockIdx.x & 1;
    int tid = threadIdx.x;
    __shared__ __align__(16) float cf[NB2][12];
    __shared__ float2 s_mm;
    __shared__ float4 s_qmm;
    if (tid == 0) { s_mm = g_mnmx[bh]; s_qmm = g_qmm[bh]; }

    {
        const float* bt = g_bt + (size_t)(bh * NPART * NC) * NB2;
        for (int i = tid; i < NC * NB2; i += 256) {
            int c = i >> 6, bin = i & 63;
            float s = 0.f;
            #pragma unroll
            for (int part = 0; part < NPART; part++)
                s += bt[(size_t)(part * NC) * NB2 + i];
            cf[bin][c] = s;
        }
        for (int i = tid; i < NB2; i += 256) cf[i][11] = 0.f;
    }
    __syncthreads();

    float mn = s_mm.x, mx = s_mm.y;
    float w = fmaxf(mx - mn, 1e-20f) * (1.0f / NB2);
    const float LN2 = 0.69314718055994530942f;

    int node = half * 256 + tid;
    float a2 = fmaf((float)(node - 2), s_qmm.y, s_qmm.x);
    float a  = a2 * LN2;
    float nM = -((a2 >= 0.f) ? a2 * mx : a2 * mn);
    float rd = ex2f(a2 * w);

    float acc0 = 0.f, acc1 = 0.f;
    #pragma unroll 1
    for (int seg = 0; seg < 4; seg++) {
        float kb = fmaf((float)(seg * 16) + 0.5f, w, mn);
        float e  = ex2f(fmaf(a2, kb, nM));
        float accs = 0.f;
        #pragma unroll
        for (int t = 0; t < 16; t++) {
            int bin = seg * 16 + t;
            float4 A = *(const float4*)&cf[bin][0];
            float4 B = *(const float4*)&cf[bin][4];
            float4 C = *(const float4*)&cf[bin][8];
            float p = C.z;
            p = fmaf(a, p, C.y);
            p = fmaf(a, p, C.x);
            p = fmaf(a, p, B.w);
            p = fmaf(a, p, B.z);
            p = fmaf(a, p, B.y);
            p = fmaf(a, p, B.x);
            p = fmaf(a, p, A.w);
            p = fmaf(a, p, A.z);
            p = fmaf(a, p, A.y);
            p = fmaf(a, p, A.x);
            accs = fmaf(e, p, accs);
            e *= rd;
        }
        if (seg & 1) acc1 += accs; else acc0 += accs;
    }
    float denom = acc0 + acc1;
    g_tab[(bh << 9) + node] = lg2f(denom) - nM;
}

// ---------------------------------------------------------------------------
// K_diag: per query, Catmull-Rom cubic on g_tab -> g(a2); diag = 2^(a2*ki - g).
//   grid 512 = 64bh x 8 chunks; 256 threads.
// ---------------------------------------------------------------------------
__global__ void __launch_bounds__(256) k_diag() {
    int bh = blockIdx.x >> 3, ic = blockIdx.x & 7;
    int tid = threadIdx.x;
    __shared__ __align__(16) float gt[NNODE];
    __shared__ float4 s_qmm;
    if (tid == 0) s_qmm = g_qmm[bh];
    if (tid < 128)
        ((float4*)gt)[tid] = ((const float4*)(g_tab + (bh << 9)))[tid];
    __syncthreads();

    const float C2 = 0.125f * 1.44269504088896340736f;
    int i = (ic << 8) + tid;
    float a2 = C2 * g_Qs[((size_t)bh << 11) + i];
    float x  = fmaf(a2 - s_qmm.x, s_qmm.z, 2.0f);
    int i0 = (int)floorf(x);
    i0 = min(max(i0, 1), 509);
    float t = x - (float)i0;

    float g0 = gt[i0 - 1], g1 = gt[i0], g2 = gt[i0 + 1], g3 = gt[i0 + 2];
    float m1 = 0.5f * (g2 - g0);
    float m2 = 0.5f * (g3 - g1);
    float dg = g2 - g1;
    float c2v = 3.f * dg - 2.f * m1 - m2;
    float c3v = -2.f * dg + m1 + m2;
    float g = g1 + t * (m1 + t * (c2v + t * c3v));

    float ki = g_Ks[((size_t)bh << 11) + i];
    float delta = fmaf(a2, ki, -g);
    g_diag[((size_t)bh << 11) + i] = ex2f(delta);
}

// ---------------------------------------------------------------------------
// K4: Y[b,p,n] = sum_h diag[b,h,p]*U[b,h,n] + bias[n].
//   grid 256 = 4b x 64pt (32p); thread = 4 consecutive n, u4[16] in regs
//   (coalesced LDG.128), diag broadcast from 2KB smem tile.
// ---------------------------------------------------------------------------
__global__ void __launch_bounds__(256) k_out(const float* __restrict__ bias,
                                             float* __restrict__ Y) {
    int pt = blockIdx.x & 63;
    int b  = blockIdx.x >> 6;
    int tid = threadIdx.x;
    __shared__ float dsm[HH * 32];
    #pragma unroll
    for (int r = 0; r < 2; r++) {
        int idx = r * 256 + tid;
        int h = idx >> 5, pl = idx & 31;
        dsm[h * 32 + pl] = g_diag[(((size_t)(b * HH + h)) << 11) + pt * 32 + pl];
    }
    __syncthreads();

    int n0 = tid << 2;
    float4 u4[HH];
    #pragma unroll
    for (int h = 0; h < HH; h++)
        u4[h] = *(const float4*)(g_U + ((b * HH + h) << 10) + n0);
    float4 bn = *(const float4*)(bias + n0);

    float4* out = (float4*)(Y + (((size_t)(b * PP + pt * 32)) << 10) + n0);
    #pragma unroll 2
    for (int p = 0; p < 32; p++) {
        float4 acc = bn;
        #pragma unroll
        for (int h = 0; h < HH; h++) {
            float d = dsm[h * 32 + p];
            acc.x = fmaf(u4[h].x, d, acc.x);
            acc.y = fmaf(u4[h].y, d, acc.y);
            acc.z = fmaf(u4[h].z, d, acc.z);
            acc.w = fmaf(u4[h].w, d, acc.w);
        }
        out[(size_t)p << 8] = acc;
    }
}

extern "C" void kernel_launch(void* const* d_in, const int* in_sizes, int n_in,
                              void* d_out, int out_size) {
    const float* Q    = (const float*)d_in[0];
    const float* K    = (const float*)d_in[1];
    const float* V    = (const float*)d_in[2];
    const float* W    = (const float*)d_in[3];
    const float* bias = (const float*)d_in[4];
    float* Y = (float*)d_out;

    k_reduce<<<8704, 256>>>(Q, K, V);
    k_mid<<<832, 256>>>(W);
    k_nodes<<<128, 256>>>();
    k_diag<<<512, 256>>>();
    k_out<<<256, 256>>>(bias, Y);
}